// round 8
// baseline (speedup 1.0000x reference)
#include <cuda_runtime.h>
#include <math_constants.h>

#define NDIM  512
#define NKNOT 32
#define NDATA 65536
#define NBIN  (NKNOT + 1)     // 33: tail-low + 31 interior + tail-high

#define DT   32               // dims per block tile
#define TPB  256              // 16 dim-pairs x 16 row-lanes
#define RPB  128              // rows per block
#define TAILW 64.0f           // tail fake-bin width (power of 2 -> exact xi)

// Tables in permuted dim order: within a 32-dim tile, dim dt maps to
// p = 16*(dt&1) + (dt>>1). Gather phase banks = 4*lp -> conflict-free.
//   RA = {t0 = -x_lo/dx, inv_dx, a2, a1}   (P = a2 xi^2 + a1 xi + a0)
//   RB = {a0, c, s, e1 = 2(s - dl)}        (den = -c xi^2 + c xi + s,
//                                           num =  c xi^2 + e1 xi + dl)
__device__ float4 g_RA[NBIN * NDIM];
__device__ float4 g_RB[NBIN * NDIM];
__device__ float4 g_P2[4 * NDIM];            // {xx[8q+1], xx[8q+3], xx[8q+5], 0}
__device__ float  g_XE[(NKNOT / 2) * NDIM];  // xx[2j]
__device__ float4 g_P1[NDIM];                // natural order: {xx7, xx15, xx23, xx31}

// ---------------------------------------------------------------------------
__global__ void prep_kernel(const float* __restrict__ params) {
    int d = blockIdx.x * blockDim.x + threadIdx.x;
    if (d >= NDIM) return;

    const float* logdx    = params + 2 * NDIM + d * (NKNOT - 1);
    const float* logdy    = params + 2 * NDIM + NDIM * (NKNOT - 1) + d * (NKNOT - 1);
    const float* logderiv = params + 2 * NDIM + 2 * NDIM * (NKNOT - 1) + d * NKNOT;

    float xx[NKNOT], yy[NKNOT], dd[NKNOT];
    xx[0] = params[d];
    yy[0] = params[NDIM + d];
    dd[0] = expf(logderiv[0]);
    #pragma unroll
    for (int k = 1; k < NKNOT; k++) {
        xx[k] = xx[k - 1] + expf(logdx[k - 1]);
        yy[k] = yy[k - 1] + expf(logdy[k - 1]);
        dd[k] = expf(logderiv[k]);
    }

    const int dt = d & (DT - 1);
    const int dp = (d & ~(DT - 1)) + 16 * (dt & 1) + (dt >> 1);  // permuted

    auto emit = [&](int b, float x_lo, float dx, float y_lo, float dy,
                    float dl, float dh) {
        const float inv_dx = 1.0f / dx;
        const float s = dy * inv_dx;
        const float c = dh + dl - 2.0f * s;
        const float a0 = y_lo * s;
        const float a1 = y_lo * c + dy * dl;
        const float a2 = -y_lo * c + dy * (s - dl);
        g_RA[b * NDIM + dp] = make_float4(-x_lo * inv_dx, inv_dx, a2, a1);
        g_RB[b * NDIM + dp] = make_float4(a0, c, s, 2.0f * (s - dl));
    };

    emit(0, xx[0] - TAILW, TAILW, yy[0] - TAILW * dd[0], TAILW * dd[0], dd[0], dd[0]);
    #pragma unroll
    for (int b = 1; b < NKNOT; b++)
        emit(b, xx[b - 1], xx[b] - xx[b - 1], yy[b - 1], yy[b] - yy[b - 1],
             dd[b - 1], dd[b]);
    emit(NKNOT, xx[NKNOT - 1], TAILW, yy[NKNOT - 1], TAILW * dd[NKNOT - 1],
         dd[NKNOT - 1], dd[NKNOT - 1]);

    #pragma unroll
    for (int q = 0; q < 4; q++)
        g_P2[q * NDIM + dp] = make_float4(xx[8 * q + 1], xx[8 * q + 3], xx[8 * q + 5], 0.0f);
    #pragma unroll
    for (int j = 0; j < NKNOT / 2; j++)
        g_XE[j * NDIM + dp] = xx[2 * j];

    g_P1[d] = make_float4(xx[7], xx[15], xx[23], xx[NKNOT - 1]);  // natural order
}

// ---------------------------------------------------------------------------
__device__ __forceinline__ void eval_one(
    const float xv, const int p, const float4 p1,
    const float4* __restrict__ sRAB, const float4* __restrict__ sP2,
    const float* __restrict__ sXE, float& yv, float& ldv)
{
    // Tournament: b = #{knots < xv} in [0, 32]
    const int q = (p1.x < xv) + (p1.y < xv) + (p1.z < xv);
    const float4 p2 = sP2[q * DT + p];
    const int t = (p2.x < xv) + (p2.y < xv) + (p2.z < xv);
    const int j = 4 * q + t;
    const int b = 2 * j + (sXE[j * DT + p] < xv) + (p1.w < xv);

    const int rec = (b * DT + p) * 2;
    const float4 rA = sRAB[rec];       // {t0, inv_dx, a2, a1}
    const float4 rB = sRAB[rec + 1];   // {a0, c, s, e1}  (imm offset +16B)

    // Horner rational-quadratic evaluation
    const float xi   = fmaf(xv, rA.y, rA.x);
    const float P    = fmaf(fmaf(rA.z, xi, rA.w), xi, rB.x);
    const float den  = fmaf(fmaf(-rB.y, xi, rB.y), xi, rB.z);  // > 0 always
    const float rden = __fdividef(1.0f, den);
    yv = P * rden;
    const float dl   = fmaf(-0.5f, rB.w, rB.z);                // dl = s - e1/2
    const float num  = fmaf(fmaf(rB.y, xi, rB.w), xi, dl);
    const float rs   = rB.z * rden;                            // s / den
    ldv = __logf(rs * rs * num);                               // s^2 num / den^2
}

// Warp = 16 dim-pairs x 2 rows; LDG.64/STG.64 = two 128B sectors per warp op.
__global__ __launch_bounds__(TPB, 5) void spline_kernel(
    const float* __restrict__ x, float* __restrict__ out)
{
    __shared__ float4 sRAB[NBIN * DT * 2];      // 33 KB (RA/RB interleaved)
    __shared__ float4 sP2[4 * DT];              // 2 KB
    __shared__ float  sXE[(NKNOT / 2) * DT];    // 2 KB

    const int dbase = blockIdx.x * DT;
    const int tid = threadIdx.x;

    for (int i = tid; i < NBIN * DT; i += TPB) {
        int g = (i >> 5) * NDIM + dbase + (i & 31);
        sRAB[2 * i]     = g_RA[g];
        sRAB[2 * i + 1] = g_RB[g];
    }
    if (tid < 4 * DT)
        sP2[tid] = g_P2[(tid >> 5) * NDIM + dbase + (tid & 31)];
    for (int i = tid; i < (NKNOT / 2) * DT; i += TPB)
        sXE[i] = g_XE[(i >> 5) * NDIM + dbase + (i & 31)];

    const int lp = tid & 15;             // dim-pair lane
    const int rl = tid >> 4;             // row lane 0..15
    const int r0 = blockIdx.y * RPB;
    const int pA = lp;                   // permuted index, dims 2lp (i=0)
    const int pB = 16 + lp;              // permuted index, dims 2lp+1 (i=1)

    // Per-thread L1 pivots for both dims (L2-cached global reads).
    const float4 p1a = g_P1[dbase + 2 * lp];
    const float4 p1b = g_P1[dbase + 2 * lp + 1];

    __syncthreads();

    float* __restrict__ yout  = out;
    float* __restrict__ ldout = out + NDATA * NDIM;

    unsigned off = (unsigned)(r0 + rl) * NDIM + dbase + 2 * lp;
    const unsigned step = (TPB / 16) * NDIM;

    #pragma unroll 2
    for (int rr = rl; rr < RPB; rr += TPB / 16, off += step) {
        const float2 xv2 = *reinterpret_cast<const float2*>(x + off);

        float ya, lda, yb, ldb;
        eval_one(xv2.x, pA, p1a, sRAB, sP2, sXE, ya, lda);
        eval_one(xv2.y, pB, p1b, sRAB, sP2, sXE, yb, ldb);

        *reinterpret_cast<float2*>(yout  + off) = make_float2(ya, yb);
        *reinterpret_cast<float2*>(ldout + off) = make_float2(lda, ldb);
    }
}

extern "C" void kernel_launch(void* const* d_in, const int* in_sizes, int n_in,
                              void* d_out, int out_size) {
    const float* x      = (const float*)d_in[0];
    const float* params = (const float*)d_in[1];
    float* out = (float*)d_out;

    prep_kernel<<<(NDIM + 255) / 256, 256>>>(params);

    dim3 grid(NDIM / DT, NDATA / RPB);
    spline_kernel<<<grid, TPB>>>(x, out);
}

// round 10
// speedup vs baseline: 1.2769x; 1.2769x over previous
#include <cuda_runtime.h>
#include <math_constants.h>

#define NDIM  512
#define NKNOT 32
#define NDATA 65536
#define NBIN  (NKNOT + 1)     // 33: tail-low + 31 interior + tail-high

#define DT   32               // dims per block tile
#define TPB  256              // 16 dim-pairs x 16 row-lanes
#define RPB  128              // rows per block
#define TAILW 64.0f           // tail fake-bin width (power of 2 -> exact xi)
#define XES  33               // padded stride for sXE (kills p-repeat conflicts)

// Tables in permuted dim order: within a 32-dim tile, dim dt maps to
// p = 16*(dt&1) + (dt>>1).
//   RA = {t0 = -x_lo/dx, inv_dx, a2, a1}   (P = a2 xi^2 + a1 xi + a0)
//   RB = {a0, c, s, e1 = 2(s - dl)}        (den = -c xi^2 + c xi + s,
//                                           num =  c xi^2 + e1 xi + dl)
__device__ float4 g_RA[NBIN * NDIM];
__device__ float4 g_RB[NBIN * NDIM];
__device__ float4 g_P2[4 * NDIM];            // {xx[8q+1], xx[8q+3], xx[8q+5], 0}
__device__ float  g_XE[(NKNOT / 2) * NDIM];  // xx[2j]
__device__ float4 g_P1[NDIM];                // natural order: {xx7, xx15, xx23, xx31}

// ---------------------------------------------------------------------------
// Prep: one warp per dim. Inclusive shfl-scan builds xx/yy; lane k holds
// knot k. Bin b (1..31) emitted by lane b from (prev-lane, own) knots.
// ---------------------------------------------------------------------------
__device__ __forceinline__ void emit_rec(int b, int dp, float x_lo, float dx,
                                         float y_lo, float dy, float dl, float dh) {
    const float inv_dx = 1.0f / dx;
    const float s = dy * inv_dx;
    const float c = dh + dl - 2.0f * s;
    g_RA[b * NDIM + dp] = make_float4(-x_lo * inv_dx, inv_dx,
                                      -y_lo * c + dy * (s - dl),
                                      y_lo * c + dy * dl);
    g_RB[b * NDIM + dp] = make_float4(y_lo * s, c, s, 2.0f * (s - dl));
}

__global__ void prep_kernel(const float* __restrict__ params) {
    const unsigned FULL = 0xFFFFFFFFu;
    const int d    = (blockIdx.x * blockDim.x + threadIdx.x) >> 5;  // dim = warp
    const int lane = threadIdx.x & 31;
    if (d >= NDIM) return;

    float edx = 0.0f, edy = 0.0f;
    if (lane >= 1) {
        edx = expf(params[2 * NDIM + d * (NKNOT - 1) + lane - 1]);
        edy = expf(params[2 * NDIM + NDIM * (NKNOT - 1) + d * (NKNOT - 1) + lane - 1]);
    }
    const float dd = expf(params[2 * NDIM + 2 * NDIM * (NKNOT - 1) + d * NKNOT + lane]);

    #pragma unroll
    for (int o = 1; o < 32; o <<= 1) {
        const float tx = __shfl_up_sync(FULL, edx, o);
        const float ty = __shfl_up_sync(FULL, edy, o);
        if (lane >= o) { edx += tx; edy += ty; }
    }
    const float xx = params[d] + edx;         // lane k holds xx[k]
    const float yy = params[NDIM + d] + edy;  // lane k holds yy[k]

    const float xxp = __shfl_up_sync(FULL, xx, 1);
    const float yyp = __shfl_up_sync(FULL, yy, 1);
    const float ddp = __shfl_up_sync(FULL, dd, 1);

    const int dt = d & (DT - 1);
    const int dp = (d & ~(DT - 1)) + 16 * (dt & 1) + (dt >> 1);   // permuted

    if (lane == 0)
        emit_rec(0, dp, xx - TAILW, TAILW, yy - TAILW * dd, TAILW * dd, dd, dd);
    else
        emit_rec(lane, dp, xxp, xx - xxp, yyp, yy - yyp, ddp, dd);
    if (lane == NKNOT - 1)
        emit_rec(NKNOT, dp, xx, TAILW, yy, TAILW * dd, dd, dd);

    // P2 pivots (lanes 0..3 write quadrant q = lane)
    const int q = lane & 3;
    const float x1 = __shfl_sync(FULL, xx, 8 * q + 1);
    const float x3 = __shfl_sync(FULL, xx, 8 * q + 3);
    const float x5 = __shfl_sync(FULL, xx, 8 * q + 5);
    if (lane < 4)
        g_P2[lane * NDIM + dp] = make_float4(x1, x3, x5, 0.0f);

    // Even-knot table (lanes 0..15 write j = lane)
    const float xe = __shfl_sync(FULL, xx, 2 * (lane & 15));
    if (lane < 16)
        g_XE[lane * NDIM + dp] = xe;

    // L1 pivots (natural dim order)
    const float p7  = __shfl_sync(FULL, xx, 7);
    const float p15 = __shfl_sync(FULL, xx, 15);
    const float p23 = __shfl_sync(FULL, xx, 23);
    const float p31 = __shfl_sync(FULL, xx, 31);
    if (lane == 0)
        g_P1[d] = make_float4(p7, p15, p23, p31);
}

// ---------------------------------------------------------------------------
__device__ __forceinline__ void eval_one(
    const float xv, const int p, const float4 p1,
    const float4* __restrict__ sRA, const float4* __restrict__ sRB,
    const float4* __restrict__ sP2, const float* __restrict__ sXE,
    float& yv, float& ldv)
{
    // Tournament: b = #{knots < xv} in [0, 32]
    const int q = (p1.x < xv) + (p1.y < xv) + (p1.z < xv);
    const float4 p2 = sP2[q * DT + p];
    const int t = (p2.x < xv) + (p2.y < xv) + (p2.z < xv);
    const int j = 4 * q + t;
    const int b = 2 * j + (sXE[j * XES + p] < xv) + (p1.w < xv);

    const int rec = b * DT + p;            // word stride 4 -> conflict-free
    const float4 rA = sRA[rec];            // {t0, inv_dx, a2, a1}
    const float4 rB = sRB[rec];            // {a0, c, s, e1}

    // Horner rational-quadratic evaluation
    const float xi   = fmaf(xv, rA.y, rA.x);
    const float P    = fmaf(fmaf(rA.z, xi, rA.w), xi, rB.x);
    const float den  = fmaf(fmaf(-rB.y, xi, rB.y), xi, rB.z);  // > 0 always
    const float rden = __fdividef(1.0f, den);
    yv = P * rden;
    const float dl   = fmaf(-0.5f, rB.w, rB.z);                // dl = s - e1/2
    const float num  = fmaf(fmaf(rB.y, xi, rB.w), xi, dl);
    const float rs   = rB.z * rden;                            // s / den
    ldv = __logf(rs * rs * num);                               // s^2 num / den^2
}

// Warp = 16 dim-pairs x 2 rows; LDG.64/STG.64 = two 128B sectors per warp op.
__global__ __launch_bounds__(TPB, 5) void spline_kernel(
    const float* __restrict__ x, float* __restrict__ out)
{
    __shared__ float4 sRA[NBIN * DT];            // 16.5 KB
    __shared__ float4 sRB[NBIN * DT];            // 16.5 KB
    __shared__ float4 sP2[4 * DT];               // 2 KB
    __shared__ float  sXE[(NKNOT / 2) * XES];    // padded stride 33

    const int dbase = blockIdx.x * DT;
    const int tid = threadIdx.x;

    for (int i = tid; i < NBIN * DT; i += TPB) {
        const int g = (i >> 5) * NDIM + dbase + (i & 31);
        sRA[i] = g_RA[g];
        sRB[i] = g_RB[g];
    }
    if (tid < 4 * DT)
        sP2[tid] = g_P2[(tid >> 5) * NDIM + dbase + (tid & 31)];
    // NOTE: must be a loop — (NKNOT/2)*DT = 512 slots > TPB threads.
    for (int i = tid; i < (NKNOT / 2) * DT; i += TPB) {
        const int j = i >> 5, p = i & 31;
        sXE[j * XES + p] = g_XE[j * NDIM + dbase + p];
    }

    const int lp = tid & 15;             // dim-pair lane
    const int rl = tid >> 4;             // row lane 0..15
    const int r0 = blockIdx.y * RPB;
    const int pA = lp;                   // permuted index, dim 2lp
    const int pB = 16 + lp;              // permuted index, dim 2lp+1

    // Per-thread L1 pivots for both dims (L2-cached global reads).
    const float4 p1a = g_P1[dbase + 2 * lp];
    const float4 p1b = g_P1[dbase + 2 * lp + 1];

    __syncthreads();

    float* __restrict__ yout  = out;
    float* __restrict__ ldout = out + NDATA * NDIM;

    unsigned off = (unsigned)(r0 + rl) * NDIM + dbase + 2 * lp;
    const unsigned step = (TPB / 16) * NDIM;

    #pragma unroll 2
    for (int rr = rl; rr < RPB; rr += TPB / 16, off += step) {
        const float2 xv2 = *reinterpret_cast<const float2*>(x + off);

        float ya, lda, yb, ldb;
        eval_one(xv2.x, pA, p1a, sRA, sRB, sP2, sXE, ya, lda);
        eval_one(xv2.y, pB, p1b, sRA, sRB, sP2, sXE, yb, ldb);

        *reinterpret_cast<float2*>(yout  + off) = make_float2(ya, yb);
        *reinterpret_cast<float2*>(ldout + off) = make_float2(lda, ldb);
    }
}

extern "C" void kernel_launch(void* const* d_in, const int* in_sizes, int n_in,
                              void* d_out, int out_size) {
    const float* x      = (const float*)d_in[0];
    const float* params = (const float*)d_in[1];
    float* out = (float*)d_out;

    prep_kernel<<<(NDIM * 32 + 255) / 256, 256>>>(params);

    dim3 grid(NDIM / DT, NDATA / RPB);
    spline_kernel<<<grid, TPB>>>(x, out);
}

// round 11
// speedup vs baseline: 1.4973x; 1.1726x over previous
#include <cuda_runtime.h>
#include <math_constants.h>

#define NDIM  512
#define NKNOT 32
#define NDATA 65536
#define NBIN  (NKNOT + 1)     // 33: tail-low + 31 interior + tail-high

#define DT   32               // dims per block tile (one warp-width)
#define TPB  256              // 32 dims x 8 rows per iteration
#define RPB  256              // rows per block
#define TAILW 64.0f           // tail fake-bin width (power of 2 -> exact xi)

// Bin coefficient records, bin-major, natural dim order: g_RA/g_RB[b*NDIM + d]
//   RA = {t0 = -x_lo/dx, inv_dx, a2, a1}   (P = a2 xi^2 + a1 xi + a0)
//   RB = {a0, c, s, e1 = 2(s - dl)}        (den = -c xi^2 + c xi + s,
//                                           num =  c xi^2 + e1 xi + dl)
__device__ float4 g_RA[NBIN * NDIM];
__device__ float4 g_RB[NBIN * NDIM];
__device__ float4 g_P2[4 * NDIM];            // {xx[8q+1], xx[8q+3], xx[8q+5], 0}
__device__ float  g_XE[(NKNOT / 2) * NDIM];  // xx[2j]
__device__ float4 g_P1[NDIM];                // {xx7, xx15, xx23, xx31}

// ---------------------------------------------------------------------------
// Prep: one warp per dim. Inclusive shfl-scan builds xx/yy; lane k holds
// knot k. Bin b (1..31) emitted by lane b from (prev-lane, own) knots.
// ---------------------------------------------------------------------------
__device__ __forceinline__ void emit_rec(int b, int d, float x_lo, float dx,
                                         float y_lo, float dy, float dl, float dh) {
    const float inv_dx = 1.0f / dx;
    const float s = dy * inv_dx;
    const float c = dh + dl - 2.0f * s;
    g_RA[b * NDIM + d] = make_float4(-x_lo * inv_dx, inv_dx,
                                     -y_lo * c + dy * (s - dl),
                                     y_lo * c + dy * dl);
    g_RB[b * NDIM + d] = make_float4(y_lo * s, c, s, 2.0f * (s - dl));
}

__global__ void prep_kernel(const float* __restrict__ params) {
    const unsigned FULL = 0xFFFFFFFFu;
    const int d    = (blockIdx.x * blockDim.x + threadIdx.x) >> 5;  // dim = warp
    const int lane = threadIdx.x & 31;
    if (d >= NDIM) return;

    float edx = 0.0f, edy = 0.0f;
    if (lane >= 1) {
        edx = expf(params[2 * NDIM + d * (NKNOT - 1) + lane - 1]);
        edy = expf(params[2 * NDIM + NDIM * (NKNOT - 1) + d * (NKNOT - 1) + lane - 1]);
    }
    const float dd = expf(params[2 * NDIM + 2 * NDIM * (NKNOT - 1) + d * NKNOT + lane]);

    #pragma unroll
    for (int o = 1; o < 32; o <<= 1) {
        const float tx = __shfl_up_sync(FULL, edx, o);
        const float ty = __shfl_up_sync(FULL, edy, o);
        if (lane >= o) { edx += tx; edy += ty; }
    }
    const float xx = params[d] + edx;         // lane k holds xx[k]
    const float yy = params[NDIM + d] + edy;  // lane k holds yy[k]

    const float xxp = __shfl_up_sync(FULL, xx, 1);
    const float yyp = __shfl_up_sync(FULL, yy, 1);
    const float ddp = __shfl_up_sync(FULL, dd, 1);

    if (lane == 0)
        emit_rec(0, d, xx - TAILW, TAILW, yy - TAILW * dd, TAILW * dd, dd, dd);
    else
        emit_rec(lane, d, xxp, xx - xxp, yyp, yy - yyp, ddp, dd);
    if (lane == NKNOT - 1)
        emit_rec(NKNOT, d, xx, TAILW, yy, TAILW * dd, dd, dd);

    // P2 pivots (lanes 0..3 write quadrant q = lane)
    const int q = lane & 3;
    const float x1 = __shfl_sync(FULL, xx, 8 * q + 1);
    const float x3 = __shfl_sync(FULL, xx, 8 * q + 3);
    const float x5 = __shfl_sync(FULL, xx, 8 * q + 5);
    if (lane < 4)
        g_P2[lane * NDIM + d] = make_float4(x1, x3, x5, 0.0f);

    // Even-knot table (lanes 0..15 write j = lane)
    const float xe = __shfl_sync(FULL, xx, 2 * (lane & 15));
    if (lane < 16)
        g_XE[lane * NDIM + d] = xe;

    // L1 pivots
    const float p7  = __shfl_sync(FULL, xx, 7);
    const float p15 = __shfl_sync(FULL, xx, 15);
    const float p23 = __shfl_sync(FULL, xx, 23);
    const float p31 = __shfl_sync(FULL, xx, 31);
    if (lane == 0)
        g_P1[d] = make_float4(p7, p15, p23, p31);
}

// ---------------------------------------------------------------------------
// Main kernel (R6 shape): 32-dim tile, 256-row slab. Branchless bin search in
// [0,32]; unified Horner rational-quadratic evaluation. Gathers = 2x LDS.128,
// bank-conflict-free for any data-dependent bin.
// ---------------------------------------------------------------------------
__global__ __launch_bounds__(TPB, 6) void spline_kernel(
    const float* __restrict__ x, float* __restrict__ out)
{
    __shared__ float4 sRA[NBIN * DT];           // 16.5 KB
    __shared__ float4 sRB[NBIN * DT];           // 16.5 KB
    __shared__ float4 sP2[4 * DT];              // 2 KB
    __shared__ float  sXE[(NKNOT / 2) * DT];    // 2 KB

    const int dbase = blockIdx.x * DT;
    const int tid = threadIdx.x;

    #pragma unroll
    for (int i = tid; i < NBIN * DT; i += TPB) {
        int g = (i >> 5) * NDIM + dbase + (i & 31);
        sRA[i] = g_RA[g];
        sRB[i] = g_RB[g];
    }
    if (tid < 4 * DT)
        sP2[tid] = g_P2[(tid >> 5) * NDIM + dbase + (tid & 31)];
    #pragma unroll
    for (int i = tid; i < (NKNOT / 2) * DT; i += TPB)
        sXE[i] = g_XE[(i >> 5) * NDIM + dbase + (i & 31)];

    const int d  = tid & 31;
    const int rl = tid >> 5;                     // 0..7
    const int r0 = blockIdx.y * RPB;

    // Per-thread L1 pivots (hoisted; p1.w = xx[31]).
    const float4 p1 = g_P1[dbase + d];

    __syncthreads();

    float* __restrict__ yout  = out;
    float* __restrict__ ldout = out + NDATA * NDIM;

    unsigned off = (unsigned)(r0 + rl) * NDIM + dbase + d;
    const unsigned step = (TPB / DT) * NDIM;

    #pragma unroll 4
    for (int rr = rl; rr < RPB; rr += TPB / DT, off += step) {
        const float xv = __ldg(x + off);

        // --- tournament: b = #{knots < xv} in [0, 32] ---
        const int q = (p1.x < xv) + (p1.y < xv) + (p1.z < xv);
        const float4 p2 = sP2[q * DT + d];
        const int t = (p2.x < xv) + (p2.y < xv) + (p2.z < xv);
        const int j = 4 * q + t;
        const int b = 2 * j + (sXE[j * DT + d] < xv) + (p1.w < xv);

        const int rec = b * DT + d;
        const float4 rA = sRA[rec];   // {t0, inv_dx, a2, a1}
        const float4 rB = sRB[rec];   // {a0, c, s, e1}

        // --- Horner rational-quadratic evaluation ---
        const float xi   = fmaf(xv, rA.y, rA.x);
        const float P    = fmaf(fmaf(rA.z, xi, rA.w), xi, rB.x);
        const float den  = fmaf(fmaf(-rB.y, xi, rB.y), xi, rB.z);  // > 0 always
        const float rden = __fdividef(1.0f, den);
        const float yv   = P * rden;
        const float dl   = fmaf(-0.5f, rB.w, rB.z);                // dl = s - e1/2
        const float num  = fmaf(fmaf(rB.y, xi, rB.w), xi, dl);
        const float rs   = rB.z * rden;                            // s / den
        const float larg = rs * rs * num;                          // s^2 num / den^2

        yout[off]  = yv;
        ldout[off] = __logf(larg);
    }
}

extern "C" void kernel_launch(void* const* d_in, const int* in_sizes, int n_in,
                              void* d_out, int out_size) {
    const float* x      = (const float*)d_in[0];
    const float* params = (const float*)d_in[1];
    float* out = (float*)d_out;

    prep_kernel<<<(NDIM * 32 + 255) / 256, 256>>>(params);

    dim3 grid(NDIM / DT, NDATA / RPB);
    spline_kernel<<<grid, TPB>>>(x, out);
}